// round 2
// baseline (speedup 1.0000x reference)
#include <cuda_runtime.h>
#include <cuda_bf16.h>

#define NN 100000
#define NE 1600000
#define NG 512
#define DIM 128
#define NC 10
#define SCAN_B 1024
#define NBLK ((NN + SCAN_B - 1) / SCAN_B)

// ---------------- scratch (device globals: allocation-free rule) --------------
__device__ int   g_is64;              // 1 if index inputs are int64, 0 if int32
__device__ int   g_deg[NN];
__device__ float g_dinv[NN];
__device__ int   g_off[NN + 1];
__device__ int   g_pos[NN];
__device__ int   g_src[NE];
__device__ int   g_bsum[NBLK];
__device__ float g_xw[(size_t)NN * DIM];   // GEMM output (per layer)
__device__ float g_h[(size_t)NN * DIM];    // aggregation output (per layer)
__device__ float g_pool[NG * DIM];
__device__ float g_cnt[NG];

// index loader honoring detected dtype
__device__ __forceinline__ int idx_at(const void* p, long long i, int is64) {
    return is64 ? (int)((const long long*)p)[i] : ((const int*)p)[i];
}

// ---------------- dtype probe -------------------------------------------------
// edge values are uniform in [0,100000); under int32 storage the odd 32-bit
// words are random nonzero values, under int64 they are all high-words == 0.
__global__ void k_probe(const void* ei) {
    if (threadIdx.x == 0 && blockIdx.x == 0) {
        const int* w = (const int*)ei;
        int nz = 0;
        for (int i = 0; i < 128; ++i) nz += (w[2 * i + 1] != 0);
        g_is64 = (nz == 0) ? 1 : 0;
    }
}

// ---------------- setup kernels ----------------------------------------------
__global__ void k_zero() {
    int i = blockIdx.x * blockDim.x + threadIdx.x;
    int stride = gridDim.x * blockDim.x;
    for (int j = i; j < NN; j += stride) g_deg[j] = 0;
    for (int j = i; j < NG * DIM; j += stride) g_pool[j] = 0.f;
    for (int j = i; j < NG; j += stride) g_cnt[j] = 0.f;
}

__global__ void k_hist(const void* __restrict__ ei) {
    int i = blockIdx.x * blockDim.x + threadIdx.x;
    int stride = gridDim.x * blockDim.x;
    int is64 = g_is64;
    for (int e = i; e < NE; e += stride) {
        int d = idx_at(ei, (long long)NE + e, is64);
        atomicAdd(&g_deg[d], 1);
    }
}

__global__ void k_dinv() {
    int i = blockIdx.x * blockDim.x + threadIdx.x;
    if (i < NN) g_dinv[i] = rsqrtf((float)(g_deg[i] + 1));
}

// block-level exclusive scan of g_deg -> g_off (partial), block sums -> g_bsum
__global__ void k_scan_local() {
    __shared__ int s[SCAN_B];
    int t = threadIdx.x;
    int idx = blockIdx.x * SCAN_B + t;
    int v = (idx < NN) ? g_deg[idx] : 0;
    s[t] = v;
    __syncthreads();
    for (int d = 1; d < SCAN_B; d <<= 1) {
        int x = (t >= d) ? s[t - d] : 0;
        __syncthreads();
        s[t] += x;
        __syncthreads();
    }
    if (idx < NN) g_off[idx] = s[t] - v;     // exclusive
    if (t == SCAN_B - 1) g_bsum[blockIdx.x] = s[t];
}

__global__ void k_scan_blocks() {
    if (threadIdx.x == 0 && blockIdx.x == 0) {
        int run = 0;
        for (int b = 0; b < NBLK; ++b) { int v = g_bsum[b]; g_bsum[b] = run; run += v; }
    }
}

__global__ void k_scan_add() {
    int idx = blockIdx.x * blockDim.x + threadIdx.x;
    if (idx < NN) {
        int o = g_off[idx] + g_bsum[idx / SCAN_B];
        g_off[idx] = o;
        g_pos[idx] = o;
    }
    if (idx == 0) g_off[NN] = NE;
}

__global__ void k_csr(const void* __restrict__ ei) {
    int i = blockIdx.x * blockDim.x + threadIdx.x;
    int stride = gridDim.x * blockDim.x;
    int is64 = g_is64;
    for (int e = i; e < NE; e += stride) {
        int s = idx_at(ei, e, is64);
        int d = idx_at(ei, (long long)NE + e, is64);
        int p = atomicAdd(&g_pos[d], 1);
        g_src[p] = s;
    }
}

// ---------------- SGEMM: g_xw[n,128] = A[n,128] @ W[128,128] -----------------
#define GR 64
#define GT 256
__global__ __launch_bounds__(GT) void k_gemm(const float* __restrict__ Aext,
                                             const float* __restrict__ W,
                                             int a_is_h, int n) {
    const float* A = a_is_h ? g_h : Aext;
    float* O = g_xw;
    __shared__ float xs[GR * 36];      // [row][k] stride 36
    __shared__ float ws[32 * 128];     // [k][col]
    int tid = threadIdx.x;
    int row0 = blockIdx.x * GR;
    int lane = tid & 31;
    int wy = tid >> 5;                 // warp id 0..7 -> rows wy*8..wy*8+7
    int col = lane * 4;

    float acc[8][4];
#pragma unroll
    for (int i = 0; i < 8; ++i)
#pragma unroll
        for (int j = 0; j < 4; ++j) acc[i][j] = 0.f;

    for (int k0 = 0; k0 < 128; k0 += 32) {
        // stage x tile: 64 rows x 32 k
        {
            int r = tid >> 2;
            int kq = (tid & 3) * 8;
            int grow = row0 + r;
            float4 v0 = make_float4(0.f, 0.f, 0.f, 0.f), v1 = v0;
            if (grow < n) {
                v0 = *(const float4*)&A[(size_t)grow * 128 + k0 + kq];
                v1 = *(const float4*)&A[(size_t)grow * 128 + k0 + kq + 4];
            }
            *(float4*)&xs[r * 36 + kq] = v0;
            *(float4*)&xs[r * 36 + kq + 4] = v1;
        }
        // stage W tile: 32 k x 128 cols
#pragma unroll
        for (int p = 0; p < 4; ++p) {
            int lin = p * 1024 + tid * 4;
            int kk = lin >> 7, cc = lin & 127;
            *(float4*)&ws[kk * 128 + cc] = *(const float4*)&W[(size_t)(k0 + kk) * 128 + cc];
        }
        __syncthreads();
#pragma unroll
        for (int k = 0; k < 32; ++k) {
            float b[4];
            *(float4*)b = *(const float4*)&ws[k * 128 + col];
#pragma unroll
            for (int i = 0; i < 8; ++i) {
                float a = xs[(wy * 8 + i) * 36 + k];
                acc[i][0] += a * b[0];
                acc[i][1] += a * b[1];
                acc[i][2] += a * b[2];
                acc[i][3] += a * b[3];
            }
        }
        __syncthreads();
    }
#pragma unroll
    for (int i = 0; i < 8; ++i) {
        int grow = row0 + wy * 8 + i;
        if (grow < n) *(float4*)&O[(size_t)grow * 128 + col] = *(float4*)&acc[i][0];
    }
}

// ---------------- aggregation: one warp per destination node -----------------
// g_h[d] = dinv[d]*( g_xw[d]*dinv[d] + sum_{e: dst=d} g_xw[src]*dinv[src] ) + bias
__global__ void k_agg(const float* __restrict__ bias, int dorelu) {
    int warp = (blockIdx.x * blockDim.x + threadIdx.x) >> 5;
    if (warp >= NN) return;
    int lane = threadIdx.x & 31;
    float di = g_dinv[warp];
    const float4* xw4 = (const float4*)g_xw;

    float4 v0 = xw4[(size_t)warp * 32 + lane];
    float4 acc = make_float4(v0.x * di, v0.y * di, v0.z * di, v0.w * di);

    int e0 = g_off[warp], e1 = g_off[warp + 1];
    for (int e = e0; e < e1; e += 32) {
        int cnt = min(32, e1 - e);
        int sidx = (lane < cnt) ? g_src[e + lane] : 0;
        float dv = (lane < cnt) ? g_dinv[sidx] : 0.f;
        for (int j = 0; j < cnt; ++j) {
            int s = __shfl_sync(0xffffffffu, sidx, j);
            float w = __shfl_sync(0xffffffffu, dv, j);
            float4 v = xw4[(size_t)s * 32 + lane];
            acc.x += v.x * w;
            acc.y += v.y * w;
            acc.z += v.z * w;
            acc.w += v.w * w;
        }
    }
    float4 bb = ((const float4*)bias)[lane];
    acc.x = acc.x * di + bb.x;
    acc.y = acc.y * di + bb.y;
    acc.z = acc.z * di + bb.z;
    acc.w = acc.w * di + bb.w;
    if (dorelu) {
        acc.x = fmaxf(acc.x, 0.f);
        acc.y = fmaxf(acc.y, 0.f);
        acc.z = fmaxf(acc.z, 0.f);
        acc.w = fmaxf(acc.w, 0.f);
    }
    ((float4*)g_h)[(size_t)warp * 32 + lane] = acc;
}

// ---------------- pooling ------------------------------------------------------
__global__ void k_cnt(const void* __restrict__ batch) {
    int i = blockIdx.x * blockDim.x + threadIdx.x;
    int stride = gridDim.x * blockDim.x;
    int is64 = g_is64;
    for (int j = i; j < NN; j += stride)
        atomicAdd(&g_cnt[idx_at(batch, j, is64)], 1.f);
}

#define PNODES 256
__global__ void k_pool(const void* __restrict__ batch) {
    int t = threadIdx.x;               // feature 0..127
    int start = blockIdx.x * PNODES;
    int end = min(start + PNODES, NN);
    if (start >= NN) return;
    int is64 = g_is64;
    float acc = 0.f;
    int gprev = idx_at(batch, start, is64);
    for (int i = start; i < end; ++i) {
        int g = idx_at(batch, i, is64);
        if (g != gprev) {
            atomicAdd(&g_pool[gprev * DIM + t], acc);
            acc = 0.f;
            gprev = g;
        }
        acc += g_h[(size_t)i * DIM + t];
    }
    atomicAdd(&g_pool[gprev * DIM + t], acc);
}

__global__ void k_final(const float* __restrict__ Wc, const float* __restrict__ bc,
                        float* __restrict__ out) {
    __shared__ float gs[DIM];
    int b = blockIdx.x, t = threadIdx.x;
    float c = fmaxf(g_cnt[b], 1.f);
    gs[t] = g_pool[b * DIM + t] / c;
    __syncthreads();
    if (t < NC) {
        float s = bc[t];
#pragma unroll 16
        for (int k = 0; k < DIM; ++k) s += gs[k] * Wc[k * NC + t];
        out[b * NC + t] = s;
    }
}

// ---------------- launch -------------------------------------------------------
extern "C" void kernel_launch(void* const* d_in, const int* in_sizes, int n_in,
                              void* d_out, int out_size) {
    const float* x     = (const float*)d_in[0];
    const void*  ei    = d_in[1];
    const void*  batch = d_in[2];
    const float* W1    = (const float*)d_in[3];
    const float* b1    = (const float*)d_in[4];
    const float* W2    = (const float*)d_in[5];
    const float* b2    = (const float*)d_in[6];
    const float* Wc    = (const float*)d_in[7];
    const float* bc    = (const float*)d_in[8];
    float*       out   = (float*)d_out;

    // 0. dtype probe (int32 vs int64 indices)
    k_probe<<<1, 32>>>(ei);
    // 1. zero scratch
    k_zero<<<256, 256>>>();
    // 2. in-degree histogram
    k_hist<<<512, 256>>>(ei);
    // 3. dinv
    k_dinv<<<(NN + 255) / 256, 256>>>();
    // 4-6. exclusive scan -> CSR offsets
    k_scan_local<<<NBLK, SCAN_B>>>();
    k_scan_blocks<<<1, 32>>>();
    k_scan_add<<<(NN + 255) / 256, 256>>>();
    // 7. CSR fill
    k_csr<<<512, 256>>>(ei);

    int gemm_blocks = (NN + GR - 1) / GR;
    int agg_blocks = (NN * 32 + 255) / 256;

    // layer 1
    k_gemm<<<gemm_blocks, GT>>>(x, W1, 0, NN);
    k_agg<<<agg_blocks, 256>>>(b1, 1);
    // layer 2
    k_gemm<<<gemm_blocks, GT>>>(nullptr, W2, 1, NN);
    k_agg<<<agg_blocks, 256>>>(b2, 0);
    // pooling + classifier
    k_cnt<<<128, 256>>>(batch);
    k_pool<<<(NN + PNODES - 1) / PNODES, DIM>>>(batch);
    k_final<<<NG, DIM>>>(Wc, bc, out);
}